// round 12
// baseline (speedup 1.0000x reference)
#include <cuda_runtime.h>

// Output == input (reference returns x reshaped bit-exactly; the attention
// machinery is deleted dead code). Pure 302 MB copy at the GB300 HBM3e
// r+w-mix ceiling (~6.55-6.60 TB/s, 82-83% of spec).
//
// Probe: write-through stores (st.global.wt) instead of .cs — eager DRAM
// write retirement, clean L2 lines, different read/write interleave at the
// memory controller. Loads stay .cs streaming.
//
// n float4 = 18,874,368 = 9216 blocks * 512 threads * 4 chunks exactly.

__device__ __forceinline__ void stwt4(float4* p, float4 v) {
    asm volatile("st.global.wt.v4.f32 [%0], {%1,%2,%3,%4};"
                 :: "l"(p), "f"(v.x), "f"(v.y), "f"(v.z), "f"(v.w) : "memory");
}

__global__ void __launch_bounds__(512) copy_wt_kernel(const float4* __restrict__ src,
                                                      float4* __restrict__ dst) {
    unsigned i = blockIdx.x * 2048u + threadIdx.x;  // 2048 = 512 threads * 4 chunks
    float4 v0 = __ldcs(src + i);
    float4 v1 = __ldcs(src + i + 512u);
    float4 v2 = __ldcs(src + i + 1024u);
    float4 v3 = __ldcs(src + i + 1536u);
    stwt4(dst + i,          v0);
    stwt4(dst + i + 512u,   v1);
    stwt4(dst + i + 1024u,  v2);
    stwt4(dst + i + 1536u,  v3);
}

// Generic fallback for unexpected sizes.
__global__ void copy_generic(const float* __restrict__ src, float* __restrict__ dst,
                             long long n) {
    long long i = (long long)blockIdx.x * blockDim.x + threadIdx.x;
    long long stride = (long long)gridDim.x * blockDim.x;
    for (; i < n; i += stride) dst[i] = src[i];
}

extern "C" void kernel_launch(void* const* d_in, const int* in_sizes, int n_in,
                              void* d_out, int out_size) {
    (void)n_in;
    long long n = out_size;
    if (n == 75497472LL && in_sizes[0] >= out_size) {
        copy_wt_kernel<<<9216, 512>>>((const float4*)d_in[0], (float4*)d_out);
    } else {
        long long nn = n;
        if ((long long)in_sizes[0] < nn) nn = in_sizes[0];
        int blocks = (int)((nn + 255) / 256);
        if (blocks > 147456) blocks = 147456;
        copy_generic<<<blocks, 256>>>((const float*)d_in[0], (float*)d_out, nn);
    }
}

// round 13
// speedup vs baseline: 1.0137x; 1.0137x over previous
#include <cuda_runtime.h>

// FINAL: Output == input (reference returns x.reshape(b,64,8,6,6).reshape(b,512,6,6)
// == x bit-exactly; 'features' and 'z' are deleted dead code). Pure 302 MB copy.
//
// Measured GB300 HBM3e r+w-mix ceiling: ~6.55-6.60 TB/s (82-83% of 8 TB/s spec).
// Exhaustively confirmed: CE memcpy, MLP={4,8,16}, 128/256-bit, block={256,512},
// one-shot/persistent, .cs/.wt stores — all within ±2% of this ceiling, this
// variant the fastest (83.3-83.9 us kernel across runs). Traffic is provably
// minimal (604 MB mandatory, zero reuse, working set >> L2). Roofline reached.
//
// One-shot exact-cover launch, monotone bid->address (DRAM page locality),
// fully unrolled/guard-free, 128-bit streaming loads+stores (.cs).
// n float4 = 18,874,368 = 9216 blocks * 512 threads * 4 chunks exactly.

__global__ void __launch_bounds__(512) copy8_kernel(const float4* __restrict__ src,
                                                    float4* __restrict__ dst) {
    unsigned i = blockIdx.x * 2048u + threadIdx.x;  // 2048 = 512 threads * 4 chunks
    float4 v0 = __ldcs(src + i);
    float4 v1 = __ldcs(src + i + 512u);
    float4 v2 = __ldcs(src + i + 1024u);
    float4 v3 = __ldcs(src + i + 1536u);
    __stcs(dst + i,          v0);
    __stcs(dst + i + 512u,   v1);
    __stcs(dst + i + 1024u,  v2);
    __stcs(dst + i + 1536u,  v3);
}

// Generic fallback for unexpected sizes.
__global__ void copy_generic(const float* __restrict__ src, float* __restrict__ dst,
                             long long n) {
    long long i = (long long)blockIdx.x * blockDim.x + threadIdx.x;
    long long stride = (long long)gridDim.x * blockDim.x;
    for (; i < n; i += stride) dst[i] = src[i];
}

extern "C" void kernel_launch(void* const* d_in, const int* in_sizes, int n_in,
                              void* d_out, int out_size) {
    (void)n_in;
    long long n = out_size;
    if (n == 75497472LL && in_sizes[0] >= out_size) {
        copy8_kernel<<<9216, 512>>>((const float4*)d_in[0], (float4*)d_out);
    } else {
        long long nn = n;
        if ((long long)in_sizes[0] < nn) nn = in_sizes[0];
        int blocks = (int)((nn + 255) / 256);
        if (blocks > 147456) blocks = 147456;
        copy_generic<<<blocks, 256>>>((const float*)d_in[0], (float*)d_out, nn);
    }
}

// round 14
// speedup vs baseline: 1.0148x; 1.0011x over previous
#include <cuda_runtime.h>

// FINAL: Output == input (reference returns x.reshape(b,64,8,6,6).reshape(b,512,6,6)
// == x bit-exactly; 'features' and 'z' are deleted dead code). Pure 302 MB copy.
//
// Measured GB300 HBM3e r+w-mix ceiling: ~6.55-6.60 TB/s (82-83% of 8 TB/s spec).
// Exhaustively confirmed: CE memcpy, MLP={1,4,8,16}, 128/256-bit, block={256,512},
// one-shot/persistent, .cs/.wt stores — all within ±2% of the ceiling, this
// variant fastest (83.3-83.9 us kernel across 5 runs). Traffic is provably
// minimal (604 MB mandatory, zero reuse, working set >> L2). Roofline reached;
// remaining end-to-end variance is harness replay jitter (~±1 us).
//
// One-shot exact-cover launch, monotone bid->address (DRAM page locality),
// fully unrolled/guard-free, 128-bit streaming loads+stores (.cs).
// n float4 = 18,874,368 = 9216 blocks * 512 threads * 4 chunks exactly.

__global__ void __launch_bounds__(512) copy8_kernel(const float4* __restrict__ src,
                                                    float4* __restrict__ dst) {
    unsigned i = blockIdx.x * 2048u + threadIdx.x;  // 2048 = 512 threads * 4 chunks
    float4 v0 = __ldcs(src + i);
    float4 v1 = __ldcs(src + i + 512u);
    float4 v2 = __ldcs(src + i + 1024u);
    float4 v3 = __ldcs(src + i + 1536u);
    __stcs(dst + i,          v0);
    __stcs(dst + i + 512u,   v1);
    __stcs(dst + i + 1024u,  v2);
    __stcs(dst + i + 1536u,  v3);
}

// Generic fallback for unexpected sizes.
__global__ void copy_generic(const float* __restrict__ src, float* __restrict__ dst,
                             long long n) {
    long long i = (long long)blockIdx.x * blockDim.x + threadIdx.x;
    long long stride = (long long)gridDim.x * blockDim.x;
    for (; i < n; i += stride) dst[i] = src[i];
}

extern "C" void kernel_launch(void* const* d_in, const int* in_sizes, int n_in,
                              void* d_out, int out_size) {
    (void)n_in;
    long long n = out_size;
    if (n == 75497472LL && in_sizes[0] >= out_size) {
        copy8_kernel<<<9216, 512>>>((const float4*)d_in[0], (float4*)d_out);
    } else {
        long long nn = n;
        if ((long long)in_sizes[0] < nn) nn = in_sizes[0];
        int blocks = (int)((nn + 255) / 256);
        if (blocks > 147456) blocks = 147456;
        copy_generic<<<blocks, 256>>>((const float*)d_in[0], (float*)d_out, nn);
    }
}

// round 15
// speedup vs baseline: 1.0187x; 1.0039x over previous
#include <cuda_runtime.h>

// Output == input (reference returns x reshaped bit-exactly; the attention
// machinery is deleted dead code). Pure 302 MB copy at the GB300 HBM3e
// r+w-mix ceiling (~6.55-6.60 TB/s, 82-83% of spec).
//
// Probe (last modifier untested): last-use loads (__ldlu) — invalidate read
// lines on consumption, freeing L2 capacity for store-burst coalescing.
// Stores stay .cs (writeback coalescing; .wt measured -1% in R12).
//
// n float4 = 18,874,368 = 9216 blocks * 512 threads * 4 chunks exactly.

__global__ void __launch_bounds__(512) copy_lu_kernel(const float4* __restrict__ src,
                                                      float4* __restrict__ dst) {
    unsigned i = blockIdx.x * 2048u + threadIdx.x;  // 2048 = 512 threads * 4 chunks
    float4 v0 = __ldlu(src + i);
    float4 v1 = __ldlu(src + i + 512u);
    float4 v2 = __ldlu(src + i + 1024u);
    float4 v3 = __ldlu(src + i + 1536u);
    __stcs(dst + i,          v0);
    __stcs(dst + i + 512u,   v1);
    __stcs(dst + i + 1024u,  v2);
    __stcs(dst + i + 1536u,  v3);
}

// Generic fallback for unexpected sizes.
__global__ void copy_generic(const float* __restrict__ src, float* __restrict__ dst,
                             long long n) {
    long long i = (long long)blockIdx.x * blockDim.x + threadIdx.x;
    long long stride = (long long)gridDim.x * blockDim.x;
    for (; i < n; i += stride) dst[i] = src[i];
}

extern "C" void kernel_launch(void* const* d_in, const int* in_sizes, int n_in,
                              void* d_out, int out_size) {
    (void)n_in;
    long long n = out_size;
    if (n == 75497472LL && in_sizes[0] >= out_size) {
        copy_lu_kernel<<<9216, 512>>>((const float4*)d_in[0], (float4*)d_out);
    } else {
        long long nn = n;
        if ((long long)in_sizes[0] < nn) nn = in_sizes[0];
        int blocks = (int)((nn + 255) / 256);
        if (blocks > 147456) blocks = 147456;
        copy_generic<<<blocks, 256>>>((const float*)d_in[0], (float*)d_out, nn);
    }
}